// round 7
// baseline (speedup 1.0000x reference)
#include <cuda_runtime.h>
#include <cuda_bf16.h>
#include <stdint.h>
#include <math.h>

// ---------------------------------------------------------------------------
// Scratch (__device__ globals -- no allocation allowed)
// ---------------------------------------------------------------------------
__device__ float g_offp[4][18 * 16384];        // partial offset-conv sums
__device__ float g_off[18 * 16384];            // offsets [b][18][h][w]
__device__ float g_raw[4 * 4096 * 256];        // pre-BN output, layout [b][hw][o]
__device__ float g_xT[4 * 4096 * 256];         // x transposed [b][h*w][c]
__device__ __align__(16) unsigned char g_wbf[36 * 65536]; // per-chunk swizzled bf16 Bh/Bl
__device__ double g_sum[256], g_sum2[256];
__device__ float g_scale[256];
__device__ float g_shift[256];

#define SWZ(x) ((x) ^ (((x) >> 3) & 0x70))

__device__ __forceinline__ uint32_t smem_to_u32(const void* p) {
    uint32_t a;
    asm("{ .reg .u64 t; cvta.to.shared.u64 t, %1; cvt.u32.u64 %0, t; }" : "=r"(a) : "l"(p));
    return a;
}

__device__ __forceinline__ void ldsm_x4(uint32_t* r, uint32_t addr) {
    asm volatile("ldmatrix.sync.aligned.m8n8.x4.shared.b16 {%0,%1,%2,%3}, [%4];"
                 : "=r"(r[0]), "=r"(r[1]), "=r"(r[2]), "=r"(r[3]) : "r"(addr));
}

__device__ __forceinline__ void mma_bf16(float* d, const uint32_t* a, const uint32_t* b) {
    asm volatile("mma.sync.aligned.m16n8k16.row.col.f32.bf16.bf16.f32 "
                 "{%0,%1,%2,%3}, {%4,%5,%6,%7}, {%8,%9}, {%0,%1,%2,%3};"
                 : "+f"(d[0]), "+f"(d[1]), "+f"(d[2]), "+f"(d[3])
                 : "r"(a[0]), "r"(a[1]), "r"(a[2]), "r"(a[3]), "r"(b[0]), "r"(b[1]));
}

__device__ __forceinline__ void cp_async16(uint32_t smem_addr, const void* gmem) {
    asm volatile("cp.async.cg.shared.global [%0], [%1], 16;"
                 :: "r"(smem_addr), "l"(gmem));
}
#define CP_COMMIT() asm volatile("cp.async.commit_group;" ::: "memory")
#define CP_WAIT0()  asm volatile("cp.async.wait_group 0;" ::: "memory")
#define CP_WAIT1()  asm volatile("cp.async.wait_group 1;" ::: "memory")

// ---------------------------------------------------------------------------
// Kernel 0 (merged prep): blocks [0,4096) transpose x -> g_xT [b][hw][c];
// blocks [4096,6400) build swizzled bf16 hi/lo B tiles + zero BN sums.
// ---------------------------------------------------------------------------
__global__ void k_prep(const float* __restrict__ x, const float* __restrict__ wdef) {
    __shared__ float t[32][33];
    if (blockIdx.x < 4096) {
        int bid = blockIdx.x;
        int b = bid >> 10, c0 = ((bid >> 7) & 7) * 32, s0 = (bid & 127) * 32;
        int si = threadIdx.x & 31, ci = threadIdx.x >> 5;
        const float* src = x + ((size_t)b * 256 + c0) * 4096 + s0;
#pragma unroll
        for (int i = 0; i < 4; i++)
            t[ci + i * 8][si] = src[(size_t)(ci + i * 8) * 4096 + si];
        __syncthreads();
        float* dst = g_xT + (size_t)b * (4096 * 256) + (size_t)s0 * 256 + c0;
#pragma unroll
        for (int i = 0; i < 4; i++)
            dst[(size_t)(ci + i * 8) * 256 + si] = t[si][ci + i * 8];
    } else {
        int v = (blockIdx.x - 4096) * 256 + threadIdx.x;   // 2304*256 = 589824
        if (v < 256) { g_sum[v] = 0.0; g_sum2[v] = 0.0; }
        int cl = v & 63;
        int o  = (v >> 6) & 255;
        int chunk = v >> 14;
        int k2 = chunk >> 2, cc = chunk & 3;
        int c = cc * 64 + cl;
        float a = wdef[((size_t)o * 256 + c) * 9 + k2];
        __nv_bfloat16 hi = __float2bfloat16(a);
        __nv_bfloat16 lo = __float2bfloat16(a - __bfloat162float(hi));
        uint32_t byte = ((uint32_t)o << 7) + ((uint32_t)cl << 1);
        uint32_t sw = SWZ(byte);
        unsigned char* base = g_wbf + (size_t)chunk * 65536;
        *(__nv_bfloat16*)(base + sw) = hi;
        *(__nv_bfloat16*)(base + 32768 + sw) = lo;
    }
}

// ---------------------------------------------------------------------------
// Kernel 1: offset conv (18 out ch, 3x3, pad 1), split over 4 c-chunks
// ---------------------------------------------------------------------------
__global__ void __launch_bounds__(256) k_offconv(const float* __restrict__ x,
                                                 const float* __restrict__ woff) {
    __shared__ float Wsh[18 * 64 * 9];
    int pb    = blockIdx.x & 63;
    int chunk = blockIdx.x >> 6;
    int c0    = chunk * 64;

    for (int v = threadIdx.x; v < 18 * 576; v += 256) {
        int oc = v / 576;
        int rem = v % 576;
        Wsh[v] = woff[oc * 2304 + c0 * 9 + rem];
    }
    __syncthreads();

    int pid = pb * 256 + threadIdx.x;
    int b  = pid >> 12;
    int hw = pid & 4095;
    int h = hw >> 6, w = hw & 63;

    float acc[18];
#pragma unroll
    for (int i = 0; i < 18; i++) acc[i] = 0.f;

    const float* xb = x + ((size_t)b * 256 + c0) * 4096;
    bool hv0 = (h > 0), hv2 = (h < 63), wv0 = (w > 0), wv2 = (w < 63);

    for (int cl = 0; cl < 64; cl++) {
        const float* xc = xb + (size_t)cl * 4096;
        float xr[9];
#pragma unroll
        for (int dy = 0; dy < 3; dy++) {
            int hh = h + dy - 1;
            bool hv = (dy == 0) ? hv0 : ((dy == 2) ? hv2 : true);
#pragma unroll
            for (int dx = 0; dx < 3; dx++) {
                int ww = w + dx - 1;
                bool wv = (dx == 0) ? wv0 : ((dx == 2) ? wv2 : true);
                xr[dy * 3 + dx] = (hv && wv) ? xc[hh * 64 + ww] : 0.f;
            }
        }
        const float* wp = Wsh + cl * 9;
#pragma unroll
        for (int oc = 0; oc < 18; oc++) {
            const float* wo = wp + oc * 576;
            float s = acc[oc];
#pragma unroll
            for (int t = 0; t < 9; t++) s += xr[t] * wo[t];
            acc[oc] = s;
        }
    }
#pragma unroll
    for (int oc = 0; oc < 18; oc++)
        g_offp[chunk][(b * 18 + oc) * 4096 + hw] = acc[oc];
}

__global__ void k_offcomb(const float* __restrict__ boff) {
    int v = blockIdx.x * 256 + threadIdx.x;
    if (v < 294912) {
        int oc = (v >> 12) % 18;
        g_off[v] = g_offp[0][v] + g_offp[1][v] + g_offp[2][v] + g_offp[3][v] + boff[oc];
    }
}

// ---------------------------------------------------------------------------
// Kernel 2: main GEMM via mma.sync (bf16 3-product split), 2 CTAs/SM.
// CTA = 128 px x 128 o.  Grid 256.  8 warps: 4 (M=32px) x 2 (N=64o).
// B double-buffered via cp.async (prefetch next chunk before waiting).
// BN column stats fused into the epilogue (smem reduce -> double atomics).
// ---------------------------------------------------------------------------
#define A_HI 0
#define A_LO 16384
#define B0_HI 32768
#define B1_HI 65536
// lo tile always at hi + 16384
#define SWT_OFF 98304
#define SIX_OFF 100352
#define SMEM_TOTAL 102400

__global__ void __launch_bounds__(256, 2) k_mainMMA() {
    extern __shared__ __align__(128) char smem[];
    uint32_t sb32 = smem_to_u32(smem);
    float* sWt = (float*)(smem + SWT_OFF);   // [4][128]
    int*   sIx = (int*)(smem + SIX_OFF);     // [4][128]

    int tid = threadIdx.x, lane = tid & 31, wid = tid >> 5;
    int wm = wid & 3, wn = wid >> 2;
    int pt = blockIdx.x >> 1, nh = blockIdx.x & 1;
    int b = pt >> 5, h0 = (pt & 31) * 2;
    int n0 = nh * 128;

    float acc[2][8][4];
#pragma unroll
    for (int mt = 0; mt < 2; mt++)
#pragma unroll
        for (int j = 0; j < 8; j++)
#pragma unroll
            for (int r = 0; r < 4; r++) acc[mt][j][r] = 0.f;

    const float* xTb = g_xT + (size_t)b * (4096 * 256);

    // prefetch B chunk 0 into buffer 0
    {
        const char* srch = (const char*)g_wbf + (size_t)n0 * 128;
        const char* srcl = srch + 32768;
#pragma unroll
        for (int t = 0; t < 4; t++) {
            uint32_t off = (uint32_t)(t * 256 + tid) * 16;
            cp_async16(sb32 + B0_HI + off, srch + off);
            cp_async16(sb32 + B0_HI + 16384 + off, srcl + off);
        }
        CP_COMMIT();
    }

    for (int i = 0; i < 36; i++) {
        int k2 = i >> 2, cc = i & 3;
        uint32_t bbase = (i & 1) ? B1_HI : B0_HI;

        if (cc == 0) {
            if (tid < 128) {
                int px = tid;
                int h = h0 + (px >> 6), w = px & 63;
                float offy = g_off[(b * 18 + 2 * k2)     * 4096 + h * 64 + w];
                float offx = g_off[(b * 18 + 2 * k2 + 1) * 4096 + h * 64 + w];
                float py  = offy + (float)(k2 / 3) + (float)h - 1.0f;
                float pxx = offx + (float)(k2 % 3) + (float)w - 1.0f;
                float y0f = floorf(py), x0f = floorf(pxx);
                float wy1 = py - y0f, wx1 = pxx - x0f;
                float wy0 = 1.f - wy1, wx0 = 1.f - wx1;
                bool vy0 = (y0f >= 0.f)       && (y0f <= 63.f);
                bool vy1 = (y0f + 1.f >= 0.f) && (y0f + 1.f <= 63.f);
                bool vx0 = (x0f >= 0.f)       && (x0f <= 63.f);
                bool vx1 = (x0f + 1.f >= 0.f) && (x0f + 1.f <= 63.f);
                int iy0 = min(max((int)y0f, 0), 63);
                int iy1 = min(max((int)y0f + 1, 0), 63);
                int ix0 = min(max((int)x0f, 0), 63);
                int ix1 = min(max((int)x0f + 1, 0), 63);
                sIx[0 * 128 + px] = iy0 * 64 + ix0;  sWt[0 * 128 + px] = (vy0 && vx0) ? wy0 * wx0 : 0.f;
                sIx[1 * 128 + px] = iy0 * 64 + ix1;  sWt[1 * 128 + px] = (vy0 && vx1) ? wy0 * wx1 : 0.f;
                sIx[2 * 128 + px] = iy1 * 64 + ix0;  sWt[2 * 128 + px] = (vy1 && vx0) ? wy1 * wx0 : 0.f;
                sIx[3 * 128 + px] = iy1 * 64 + ix1;  sWt[3 * 128 + px] = (vy1 && vx1) ? wy1 * wx1 : 0.f;
            }
            __syncthreads();
        }

        // gather A: 128 px x 64 c (bilinear, 4 corners, float4 over c) -> bf16 hi/lo
        int c0 = cc * 64;
#pragma unroll
        for (int t = 0; t < 8; t++) {
            int task = t * 256 + tid;
            int px = task >> 4;
            int cl = (task & 15) * 4;
            float w0 = sWt[0 * 128 + px], w1 = sWt[1 * 128 + px];
            float w2 = sWt[2 * 128 + px], w3 = sWt[3 * 128 + px];
            const float4 v0 = *(const float4*)(xTb + (size_t)sIx[0 * 128 + px] * 256 + c0 + cl);
            const float4 v1 = *(const float4*)(xTb + (size_t)sIx[1 * 128 + px] * 256 + c0 + cl);
            const float4 v2 = *(const float4*)(xTb + (size_t)sIx[2 * 128 + px] * 256 + c0 + cl);
            const float4 v3 = *(const float4*)(xTb + (size_t)sIx[3 * 128 + px] * 256 + c0 + cl);
            float a0 = w0 * v0.x + w1 * v1.x + w2 * v2.x + w3 * v3.x;
            float a1 = w0 * v0.y + w1 * v1.y + w2 * v2.y + w3 * v3.y;
            float a2 = w0 * v0.z + w1 * v1.z + w2 * v2.z + w3 * v3.z;
            float a3 = w0 * v0.w + w1 * v1.w + w2 * v2.w + w3 * v3.w;
            __nv_bfloat16 h0b = __float2bfloat16(a0), h1b = __float2bfloat16(a1);
            __nv_bfloat16 h2b = __float2bfloat16(a2), h3b = __float2bfloat16(a3);
            __nv_bfloat16 l0b = __float2bfloat16(a0 - __bfloat162float(h0b));
            __nv_bfloat16 l1b = __float2bfloat16(a1 - __bfloat162float(h1b));
            __nv_bfloat16 l2b = __float2bfloat16(a2 - __bfloat162float(h2b));
            __nv_bfloat16 l3b = __float2bfloat16(a3 - __bfloat162float(h3b));
            uint2 hv, lv;
            hv.x = ((uint32_t)*(uint16_t*)&h0b) | ((uint32_t)*(uint16_t*)&h1b << 16);
            hv.y = ((uint32_t)*(uint16_t*)&h2b) | ((uint32_t)*(uint16_t*)&h3b << 16);
            lv.x = ((uint32_t)*(uint16_t*)&l0b) | ((uint32_t)*(uint16_t*)&l1b << 16);
            lv.y = ((uint32_t)*(uint16_t*)&l2b) | ((uint32_t)*(uint16_t*)&l3b << 16);
            uint32_t byte = ((uint32_t)px << 7) + ((uint32_t)cl << 1);
            uint32_t sw = SWZ(byte);
            *(uint2*)(smem + A_HI + sw) = hv;
            *(uint2*)(smem + A_LO + sw) = lv;
        }

        // prefetch next B chunk into the other buffer (overlaps current MMA)
        if (i < 35) {
            uint32_t nb = (i & 1) ? B0_HI : B1_HI;
            const char* srch = (const char*)g_wbf + (size_t)(i + 1) * 65536 + (size_t)n0 * 128;
            const char* srcl = srch + 32768;
#pragma unroll
            for (int t = 0; t < 4; t++) {
                uint32_t off = (uint32_t)(t * 256 + tid) * 16;
                cp_async16(sb32 + nb + off, srch + off);
                cp_async16(sb32 + nb + 16384 + off, srcl + off);
            }
            CP_COMMIT();
            CP_WAIT1();        // current chunk's B resident
        } else {
            CP_WAIT0();
        }
        __syncthreads();

        // MMA: 4 k16 steps, 3-product split
#pragma unroll
        for (int k16 = 0; k16 < 4; k16++) {
            uint32_t ah[2][4], al[2][4];
#pragma unroll
            for (int mt = 0; mt < 2; mt++) {
                int arow = wm * 32 + mt * 16 + (lane & 15);
                int acb  = k16 * 32 + ((lane >> 4) << 4);
                uint32_t off = SWZ((uint32_t)(arow * 128 + acb));
                ldsm_x4(ah[mt], sb32 + A_HI + off);
                ldsm_x4(al[mt], sb32 + A_LO + off);
            }
#pragma unroll
            for (int np = 0; np < 4; np++) {
                uint32_t bh[4], bl[4];
                int brow = wn * 64 + np * 16 + ((lane >> 4) << 3) + (lane & 7);
                int bcb  = k16 * 32 + ((lane & 8) << 1);
                uint32_t off = SWZ((uint32_t)(brow * 128 + bcb));
                ldsm_x4(bh, sb32 + bbase + off);
                ldsm_x4(bl, sb32 + bbase + 16384 + off);
#pragma unroll
                for (int mt = 0; mt < 2; mt++)
#pragma unroll
                    for (int jj = 0; jj < 2; jj++) {
                        int j = np * 2 + jj;
                        mma_bf16(acc[mt][j], ah[mt], &bh[jj * 2]);
                        mma_bf16(acc[mt][j], ah[mt], &bl[jj * 2]);
                        mma_bf16(acc[mt][j], al[mt], &bh[jj * 2]);
                    }
            }
        }
        __syncthreads();
    }

    // -------- epilogue: write g_raw + fused BN column stats --------
    float* ssum  = (float*)smem;             // [128] per-CTA column sums
    float* ssum2 = (float*)(smem + 1024);    // [128]
    if (tid < 128) { ssum[tid] = 0.f; ssum2[tid] = 0.f; }
    __syncthreads();

    size_t rowbase = (size_t)b * 4096 + (size_t)h0 * 64;
    float ls[16], ls2[16];
#pragma unroll
    for (int v = 0; v < 16; v++) { ls[v] = 0.f; ls2[v] = 0.f; }

#pragma unroll
    for (int mt = 0; mt < 2; mt++)
#pragma unroll
        for (int j = 0; j < 8; j++) {
            int px = wm * 32 + mt * 16 + (lane >> 2);
            int o  = n0 + wn * 64 + j * 8 + (lane & 3) * 2;
            float a0 = acc[mt][j][0], a1 = acc[mt][j][1];
            float a2 = acc[mt][j][2], a3 = acc[mt][j][3];
            *(float2*)(g_raw + (rowbase + px) * 256 + o)     = make_float2(a0, a1);
            *(float2*)(g_raw + (rowbase + px + 8) * 256 + o) = make_float2(a2, a3);
            ls[j * 2]      += a0 + a2;
            ls[j * 2 + 1]  += a1 + a3;
            ls2[j * 2]     += a0 * a0 + a2 * a2;
            ls2[j * 2 + 1] += a1 * a1 + a3 * a3;
        }
#pragma unroll
    for (int v = 0; v < 16; v++) {
        int ol = wn * 64 + (v >> 1) * 8 + (lane & 3) * 2 + (v & 1);
        atomicAdd(&ssum[ol], ls[v]);
        atomicAdd(&ssum2[ol], ls2[v]);
    }
    __syncthreads();
    if (tid < 128) {
        atomicAdd(&g_sum[n0 + tid], (double)ssum[tid]);
        atomicAdd(&g_sum2[n0 + tid], (double)ssum2[tid]);
    }
}

// ---------------------------------------------------------------------------
// Kernel 3: finalize per-channel scale/shift
// ---------------------------------------------------------------------------
__global__ void k_stats2(const float* __restrict__ gamma, const float* __restrict__ beta) {
    int o = threadIdx.x;
    double mean = g_sum[o] / 16384.0;
    double var  = g_sum2[o] / 16384.0 - mean * mean;
    float sc = gamma[o] * rsqrtf((float)var + 1e-5f);
    g_scale[o] = sc;
    g_shift[o] = beta[o] - (float)mean * sc;
}

// ---------------------------------------------------------------------------
// Kernel 4: normalize + ReLU + transpose [b][hw][o] -> out [b][o][hw]
// ---------------------------------------------------------------------------
__global__ void k_normT(float* __restrict__ out) {
    __shared__ float t[32][33];
    int r0 = blockIdx.x * 32;          // global row (b*4096 + hw)
    int o0 = blockIdx.y * 32;
    int si = threadIdx.x & 31, ri = threadIdx.x >> 5;
#pragma unroll
    for (int i = 0; i < 4; i++)
        t[ri + i * 8][si] = g_raw[(size_t)(r0 + ri + i * 8) * 256 + o0 + si];
    __syncthreads();
    int bq = r0 >> 12;
    int hw0 = r0 & 4095;
#pragma unroll
    for (int i = 0; i < 4; i++) {
        int o = o0 + ri + i * 8;
        float sc = g_scale[o], sh = g_shift[o];
        float v = t[si][ri + i * 8];
        out[((size_t)bq * 256 + o) * 4096 + hw0 + si] = fmaxf(v * sc + sh, 0.f);
    }
}

// ---------------------------------------------------------------------------
extern "C" void kernel_launch(void* const* d_in, const int* in_sizes, int n_in,
                              void* d_out, int out_size) {
    const float* x     = (const float*)d_in[0];
    const float* woff  = (const float*)d_in[1];
    const float* boff  = (const float*)d_in[2];
    const float* wdef  = (const float*)d_in[3];
    const float* gamma = (const float*)d_in[4];
    const float* beta  = (const float*)d_in[5];
    float* out = (float*)d_out;

    cudaFuncSetAttribute(k_mainMMA, cudaFuncAttributeMaxDynamicSharedMemorySize, SMEM_TOTAL);

    k_prep<<<6400, 256>>>(x, wdef);
    k_offconv<<<256, 256>>>(x, woff);
    k_offcomb<<<1152, 256>>>(boff);
    k_mainMMA<<<256, 256, SMEM_TOTAL>>>();   // launch index 3 -> ncu capture slot
    k_stats2<<<1, 256>>>(gamma, beta);
    k_normT<<<dim3(512, 8), 256>>>(out);
}

// round 8
// speedup vs baseline: 1.5794x; 1.5794x over previous
#include <cuda_runtime.h>
#include <cuda_bf16.h>
#include <stdint.h>
#include <math.h>

// ---------------------------------------------------------------------------
// Scratch (__device__ globals -- no allocation allowed)
// ---------------------------------------------------------------------------
__device__ float g_offp[4][18 * 16384];        // partial offset-conv sums
__device__ float g_xT[4 * 4096 * 256];         // x transposed [b][h*w][c]
__device__ __align__(16) unsigned char g_wbf[36 * 65536]; // per-chunk swizzled bf16 Bh/Bl
__device__ double g_sum[256], g_sum2[256];
__device__ int g_barrier;

#define SWZ(x) ((x) ^ (((x) >> 3) & 0x70))

__device__ __forceinline__ uint32_t smem_to_u32(const void* p) {
    uint32_t a;
    asm("{ .reg .u64 t; cvta.to.shared.u64 t, %1; cvt.u32.u64 %0, t; }" : "=r"(a) : "l"(p));
    return a;
}

__device__ __forceinline__ void ldsm_x4(uint32_t* r, uint32_t addr) {
    asm volatile("ldmatrix.sync.aligned.m8n8.x4.shared.b16 {%0,%1,%2,%3}, [%4];"
                 : "=r"(r[0]), "=r"(r[1]), "=r"(r[2]), "=r"(r[3]) : "r"(addr));
}

__device__ __forceinline__ void mma_bf16(float* d, const uint32_t* a, const uint32_t* b) {
    asm volatile("mma.sync.aligned.m16n8k16.row.col.f32.bf16.bf16.f32 "
                 "{%0,%1,%2,%3}, {%4,%5,%6,%7}, {%8,%9}, {%0,%1,%2,%3};"
                 : "+f"(d[0]), "+f"(d[1]), "+f"(d[2]), "+f"(d[3])
                 : "r"(a[0]), "r"(a[1]), "r"(a[2]), "r"(a[3]), "r"(b[0]), "r"(b[1]));
}

__device__ __forceinline__ void cp_async16(uint32_t smem_addr, const void* gmem) {
    asm volatile("cp.async.cg.shared.global [%0], [%1], 16;"
                 :: "r"(smem_addr), "l"(gmem));
}
#define CP_COMMIT() asm volatile("cp.async.commit_group;" ::: "memory")
#define CP_WAIT0()  asm volatile("cp.async.wait_group 0;" ::: "memory")
#define CP_WAIT1()  asm volatile("cp.async.wait_group 1;" ::: "memory")

// ---------------------------------------------------------------------------
// Kernel 0 (merged prep): blocks [0,4096) transpose x -> g_xT [b][hw][c];
// blocks [4096,6400) build swizzled bf16 hi/lo B tiles + reset sums/barrier.
// ---------------------------------------------------------------------------
__global__ void k_prep(const float* __restrict__ x, const float* __restrict__ wdef) {
    __shared__ float t[32][33];
    if (blockIdx.x < 4096) {
        int bid = blockIdx.x;
        int b = bid >> 10, c0 = ((bid >> 7) & 7) * 32, s0 = (bid & 127) * 32;
        int si = threadIdx.x & 31, ci = threadIdx.x >> 5;
        const float* src = x + ((size_t)b * 256 + c0) * 4096 + s0;
#pragma unroll
        for (int i = 0; i < 4; i++)
            t[ci + i * 8][si] = src[(size_t)(ci + i * 8) * 4096 + si];
        __syncthreads();
        float* dst = g_xT + (size_t)b * (4096 * 256) + (size_t)s0 * 256 + c0;
#pragma unroll
        for (int i = 0; i < 4; i++)
            dst[(size_t)(ci + i * 8) * 256 + si] = t[si][ci + i * 8];
    } else {
        int v = (blockIdx.x - 4096) * 256 + threadIdx.x;   // 2304*256 = 589824
        if (v < 256) { g_sum[v] = 0.0; g_sum2[v] = 0.0; }
        if (v == 0) g_barrier = 0;
        int cl = v & 63;
        int o  = (v >> 6) & 255;
        int chunk = v >> 14;
        int k2 = chunk >> 2, cc = chunk & 3;
        int c = cc * 64 + cl;
        float a = wdef[((size_t)o * 256 + c) * 9 + k2];
        __nv_bfloat16 hi = __float2bfloat16(a);
        __nv_bfloat16 lo = __float2bfloat16(a - __bfloat162float(hi));
        uint32_t byte = ((uint32_t)o << 7) + ((uint32_t)cl << 1);
        uint32_t sw = SWZ(byte);
        unsigned char* base = g_wbf + (size_t)chunk * 65536;
        *(__nv_bfloat16*)(base + sw) = hi;
        *(__nv_bfloat16*)(base + 32768 + sw) = lo;
    }
}

// ---------------------------------------------------------------------------
// Kernel 1: offset conv (18 out ch, 3x3, pad 1), split over 4 c-chunks
// ---------------------------------------------------------------------------
__global__ void __launch_bounds__(256) k_offconv(const float* __restrict__ x,
                                                 const float* __restrict__ woff) {
    __shared__ float Wsh[18 * 64 * 9];
    int pb    = blockIdx.x & 63;
    int chunk = blockIdx.x >> 6;
    int c0    = chunk * 64;

    for (int v = threadIdx.x; v < 18 * 576; v += 256) {
        int oc = v / 576;
        int rem = v % 576;
        Wsh[v] = woff[oc * 2304 + c0 * 9 + rem];
    }
    __syncthreads();

    int pid = pb * 256 + threadIdx.x;
    int b  = pid >> 12;
    int hw = pid & 4095;
    int h = hw >> 6, w = hw & 63;

    float acc[18];
#pragma unroll
    for (int i = 0; i < 18; i++) acc[i] = 0.f;

    const float* xb = x + ((size_t)b * 256 + c0) * 4096;
    bool hv0 = (h > 0), hv2 = (h < 63), wv0 = (w > 0), wv2 = (w < 63);

    for (int cl = 0; cl < 64; cl++) {
        const float* xc = xb + (size_t)cl * 4096;
        float xr[9];
#pragma unroll
        for (int dy = 0; dy < 3; dy++) {
            int hh = h + dy - 1;
            bool hv = (dy == 0) ? hv0 : ((dy == 2) ? hv2 : true);
#pragma unroll
            for (int dx = 0; dx < 3; dx++) {
                int ww = w + dx - 1;
                bool wv = (dx == 0) ? wv0 : ((dx == 2) ? wv2 : true);
                xr[dy * 3 + dx] = (hv && wv) ? xc[hh * 64 + ww] : 0.f;
            }
        }
        const float* wp = Wsh + cl * 9;
#pragma unroll
        for (int oc = 0; oc < 18; oc++) {
            const float* wo = wp + oc * 576;
            float s = acc[oc];
#pragma unroll
            for (int t = 0; t < 9; t++) s += xr[t] * wo[t];
            acc[oc] = s;
        }
    }
#pragma unroll
    for (int oc = 0; oc < 18; oc++)
        g_offp[chunk][(b * 18 + oc) * 4096 + hw] = acc[oc];
}

// ---------------------------------------------------------------------------
// Kernel 2: fully fused main: gather + bf16-split GEMM + BN stats +
// grid barrier + normalize + ReLU + direct coalesced output write.
// CTA = 128 px x 128 o.  Grid 256 (all co-resident: 2 CTAs/SM x 148 SMs >= 256).
// ---------------------------------------------------------------------------
#define A_HI 0
#define A_LO 16384
#define B0_HI 32768
#define B1_HI 65536
// lo tile always at hi + 16384
#define SWT_OFF 98304
#define SIX_OFF 100352
#define SMEM_TOTAL 102400
// epilogue reuse: stage[128][130] floats at offset 0; sc/sh at SWT_OFF

__global__ void __launch_bounds__(256, 2) k_mainMMA(const float* __restrict__ boff,
                                                    const float* __restrict__ gamma,
                                                    const float* __restrict__ beta,
                                                    float* __restrict__ out) {
    extern __shared__ __align__(128) char smem[];
    uint32_t sb32 = smem_to_u32(smem);
    float* sWt = (float*)(smem + SWT_OFF);   // [4][128]
    int*   sIx = (int*)(smem + SIX_OFF);     // [4][128]

    int tid = threadIdx.x, lane = tid & 31, wid = tid >> 5;
    int wm = wid & 3, wn = wid >> 2;
    int pt = blockIdx.x >> 1, nh = blockIdx.x & 1;
    int b = pt >> 5, h0 = (pt & 31) * 2;
    int n0 = nh * 128;

    float acc[2][8][4];
#pragma unroll
    for (int mt = 0; mt < 2; mt++)
#pragma unroll
        for (int j = 0; j < 8; j++)
#pragma unroll
            for (int r = 0; r < 4; r++) acc[mt][j][r] = 0.f;

    const float* xTb = g_xT + (size_t)b * (4096 * 256);

    // prefetch B chunk 0 into buffer 0
    {
        const char* srch = (const char*)g_wbf + (size_t)n0 * 128;
        const char* srcl = srch + 32768;
#pragma unroll
        for (int t = 0; t < 4; t++) {
            uint32_t off = (uint32_t)(t * 256 + tid) * 16;
            cp_async16(sb32 + B0_HI + off, srch + off);
            cp_async16(sb32 + B0_HI + 16384 + off, srcl + off);
        }
        CP_COMMIT();
    }

    for (int i = 0; i < 36; i++) {
        int k2 = i >> 2, cc = i & 3;
        uint32_t bbase = (i & 1) ? B1_HI : B0_HI;

        if (cc == 0) {
            if (tid < 128) {
                int px = tid;
                int h = h0 + (px >> 6), w = px & 63;
                int iy_ = (b * 18 + 2 * k2) * 4096 + h * 64 + w;
                int ix_ = iy_ + 4096;
                float offy = g_offp[0][iy_] + g_offp[1][iy_] + g_offp[2][iy_] + g_offp[3][iy_] + boff[2 * k2];
                float offx = g_offp[0][ix_] + g_offp[1][ix_] + g_offp[2][ix_] + g_offp[3][ix_] + boff[2 * k2 + 1];
                float py  = offy + (float)(k2 / 3) + (float)h - 1.0f;
                float pxx = offx + (float)(k2 % 3) + (float)w - 1.0f;
                float y0f = floorf(py), x0f = floorf(pxx);
                float wy1 = py - y0f, wx1 = pxx - x0f;
                float wy0 = 1.f - wy1, wx0 = 1.f - wx1;
                bool vy0 = (y0f >= 0.f)       && (y0f <= 63.f);
                bool vy1 = (y0f + 1.f >= 0.f) && (y0f + 1.f <= 63.f);
                bool vx0 = (x0f >= 0.f)       && (x0f <= 63.f);
                bool vx1 = (x0f + 1.f >= 0.f) && (x0f + 1.f <= 63.f);
                int iy0 = min(max((int)y0f, 0), 63);
                int iy1 = min(max((int)y0f + 1, 0), 63);
                int ix0 = min(max((int)x0f, 0), 63);
                int ix1 = min(max((int)x0f + 1, 0), 63);
                sIx[0 * 128 + px] = iy0 * 64 + ix0;  sWt[0 * 128 + px] = (vy0 && vx0) ? wy0 * wx0 : 0.f;
                sIx[1 * 128 + px] = iy0 * 64 + ix1;  sWt[1 * 128 + px] = (vy0 && vx1) ? wy0 * wx1 : 0.f;
                sIx[2 * 128 + px] = iy1 * 64 + ix0;  sWt[2 * 128 + px] = (vy1 && vx0) ? wy1 * wx0 : 0.f;
                sIx[3 * 128 + px] = iy1 * 64 + ix1;  sWt[3 * 128 + px] = (vy1 && vx1) ? wy1 * wx1 : 0.f;
            }
            __syncthreads();
        }

        // gather A: 128 px x 64 c (bilinear, 4 corners, float4 over c) -> bf16 hi/lo
        int c0 = cc * 64;
#pragma unroll
        for (int t = 0; t < 8; t++) {
            int task = t * 256 + tid;
            int px = task >> 4;
            int cl = (task & 15) * 4;
            float w0 = sWt[0 * 128 + px], w1 = sWt[1 * 128 + px];
            float w2 = sWt[2 * 128 + px], w3 = sWt[3 * 128 + px];
            const float4 v0 = *(const float4*)(xTb + (size_t)sIx[0 * 128 + px] * 256 + c0 + cl);
            const float4 v1 = *(const float4*)(xTb + (size_t)sIx[1 * 128 + px] * 256 + c0 + cl);
            const float4 v2 = *(const float4*)(xTb + (size_t)sIx[2 * 128 + px] * 256 + c0 + cl);
            const float4 v3 = *(const float4*)(xTb + (size_t)sIx[3 * 128 + px] * 256 + c0 + cl);
            float a0 = w0 * v0.x + w1 * v1.x + w2 * v2.x + w3 * v3.x;
            float a1 = w0 * v0.y + w1 * v1.y + w2 * v2.y + w3 * v3.y;
            float a2 = w0 * v0.z + w1 * v1.z + w2 * v2.z + w3 * v3.z;
            float a3 = w0 * v0.w + w1 * v1.w + w2 * v2.w + w3 * v3.w;
            __nv_bfloat16 h0b = __float2bfloat16(a0), h1b = __float2bfloat16(a1);
            __nv_bfloat16 h2b = __float2bfloat16(a2), h3b = __float2bfloat16(a3);
            __nv_bfloat16 l0b = __float2bfloat16(a0 - __bfloat162float(h0b));
            __nv_bfloat16 l1b = __float2bfloat16(a1 - __bfloat162float(h1b));
            __nv_bfloat16 l2b = __float2bfloat16(a2 - __bfloat162float(h2b));
            __nv_bfloat16 l3b = __float2bfloat16(a3 - __bfloat162float(h3b));
            uint2 hv, lv;
            hv.x = ((uint32_t)*(uint16_t*)&h0b) | ((uint32_t)*(uint16_t*)&h1b << 16);
            hv.y = ((uint32_t)*(uint16_t*)&h2b) | ((uint32_t)*(uint16_t*)&h3b << 16);
            lv.x = ((uint32_t)*(uint16_t*)&l0b) | ((uint32_t)*(uint16_t*)&l1b << 16);
            lv.y = ((uint32_t)*(uint16_t*)&l2b) | ((uint32_t)*(uint16_t*)&l3b << 16);
            uint32_t byte = ((uint32_t)px << 7) + ((uint32_t)cl << 1);
            uint32_t sw = SWZ(byte);
            *(uint2*)(smem + A_HI + sw) = hv;
            *(uint2*)(smem + A_LO + sw) = lv;
        }

        // prefetch next B chunk into the other buffer (overlaps current MMA)
        if (i < 35) {
            uint32_t nb = (i & 1) ? B0_HI : B1_HI;
            const char* srch = (const char*)g_wbf + (size_t)(i + 1) * 65536 + (size_t)n0 * 128;
            const char* srcl = srch + 32768;
#pragma unroll
            for (int t = 0; t < 4; t++) {
                uint32_t off = (uint32_t)(t * 256 + tid) * 16;
                cp_async16(sb32 + nb + off, srch + off);
                cp_async16(sb32 + nb + 16384 + off, srcl + off);
            }
            CP_COMMIT();
            CP_WAIT1();        // current chunk's B resident
        } else {
            CP_WAIT0();
        }
        __syncthreads();

        // MMA: 4 k16 steps, 3-product split
#pragma unroll
        for (int k16 = 0; k16 < 4; k16++) {
            uint32_t ah[2][4], al[2][4];
#pragma unroll
            for (int mt = 0; mt < 2; mt++) {
                int arow = wm * 32 + mt * 16 + (lane & 15);
                int acb  = k16 * 32 + ((lane >> 4) << 4);
                uint32_t off = SWZ((uint32_t)(arow * 128 + acb));
                ldsm_x4(ah[mt], sb32 + A_HI + off);
                ldsm_x4(al[mt], sb32 + A_LO + off);
            }
#pragma unroll
            for (int np = 0; np < 4; np++) {
                uint32_t bh[4], bl[4];
                int brow = wn * 64 + np * 16 + ((lane >> 4) << 3) + (lane & 7);
                int bcb  = k16 * 32 + ((lane & 8) << 1);
                uint32_t off = SWZ((uint32_t)(brow * 128 + bcb));
                ldsm_x4(bh, sb32 + bbase + off);
                ldsm_x4(bl, sb32 + bbase + 16384 + off);
#pragma unroll
                for (int mt = 0; mt < 2; mt++)
#pragma unroll
                    for (int jj = 0; jj < 2; jj++) {
                        int j = np * 2 + jj;
                        mma_bf16(acc[mt][j], ah[mt], &bh[jj * 2]);
                        mma_bf16(acc[mt][j], ah[mt], &bl[jj * 2]);
                        mma_bf16(acc[mt][j], al[mt], &bh[jj * 2]);
                    }
            }
        }
        __syncthreads();
    }

    // -------- fused BN column stats (in-register -> smem -> global) --------
    float* ssum  = (float*)smem;             // [128]
    float* ssum2 = (float*)(smem + 1024);    // [128]
    if (tid < 128) { ssum[tid] = 0.f; ssum2[tid] = 0.f; }
    __syncthreads();

    float ls[16], ls2[16];
#pragma unroll
    for (int v = 0; v < 16; v++) { ls[v] = 0.f; ls2[v] = 0.f; }
#pragma unroll
    for (int mt = 0; mt < 2; mt++)
#pragma unroll
        for (int j = 0; j < 8; j++) {
            float a0 = acc[mt][j][0], a1 = acc[mt][j][1];
            float a2 = acc[mt][j][2], a3 = acc[mt][j][3];
            ls[j * 2]      += a0 + a2;
            ls[j * 2 + 1]  += a1 + a3;
            ls2[j * 2]     += a0 * a0 + a2 * a2;
            ls2[j * 2 + 1] += a1 * a1 + a3 * a3;
        }
#pragma unroll
    for (int v = 0; v < 16; v++) {
        int ol = wn * 64 + (v >> 1) * 8 + (lane & 3) * 2 + (v & 1);
        atomicAdd(&ssum[ol], ls[v]);
        atomicAdd(&ssum2[ol], ls2[v]);
    }
    __syncthreads();
    if (tid < 128) {
        atomicAdd(&g_sum[n0 + tid], (double)ssum[tid]);
        atomicAdd(&g_sum2[n0 + tid], (double)ssum2[tid]);
    }

    // -------- grid-wide barrier (all 256 CTAs co-resident) --------
    __syncthreads();
    if (tid == 0) {
        __threadfence();
        atomicAdd(&g_barrier, 1);
        while (*(volatile int*)&g_barrier < 256) { }
        __threadfence();
    }
    __syncthreads();

    // -------- per-channel scale/shift for this CTA's 128 o --------
    float* sc = (float*)(smem + SWT_OFF);        // [128]
    float* sh = (float*)(smem + SWT_OFF + 512);  // [128]
    if (tid < 128) {
        int o = n0 + tid;
        double mean = g_sum[o] / 16384.0;
        double var  = g_sum2[o] / 16384.0 - mean * mean;
        float s = gamma[o] * rsqrtf((float)var + 1e-5f);
        sc[tid] = s;
        sh[tid] = beta[o] - (float)mean * s;
    }

    // -------- stage acc -> smem [o_local][px] (stride 130) --------
    float* stage = (float*)smem;
    __syncthreads();
#pragma unroll
    for (int mt = 0; mt < 2; mt++)
#pragma unroll
        for (int j = 0; j < 8; j++) {
            int px = wm * 32 + mt * 16 + (lane >> 2);
            int ol = wn * 64 + j * 8 + (lane & 3) * 2;
            stage[ol * 130 + px]           = acc[mt][j][0];
            stage[(ol + 1) * 130 + px]     = acc[mt][j][1];
            stage[ol * 130 + px + 8]       = acc[mt][j][2];
            stage[(ol + 1) * 130 + px + 8] = acc[mt][j][3];
        }
    __syncthreads();

    // -------- normalize + ReLU + direct coalesced write to out --------
    // out[b][o][hw]: for each o, 128 contiguous floats at h0*64
    size_t obase = ((size_t)b * 256 + n0) * 4096 + (size_t)h0 * 64;
#pragma unroll
    for (int it = 0; it < 64; it++) {
        int gi = it * 256 + tid;
        int o  = gi >> 7;
        int px = gi & 127;
        float v = stage[o * 130 + px] * sc[o] + sh[o];
        out[obase + (size_t)o * 4096 + px] = fmaxf(v, 0.f);
    }
}

// ---------------------------------------------------------------------------
extern "C" void kernel_launch(void* const* d_in, const int* in_sizes, int n_in,
                              void* d_out, int out_size) {
    const float* x     = (const float*)d_in[0];
    const float* woff  = (const float*)d_in[1];
    const float* boff  = (const float*)d_in[2];
    const float* wdef  = (const float*)d_in[3];
    const float* gamma = (const float*)d_in[4];
    const float* beta  = (const float*)d_in[5];
    float* out = (float*)d_out;

    cudaFuncSetAttribute(k_mainMMA, cudaFuncAttributeMaxDynamicSharedMemorySize, SMEM_TOTAL);

    k_prep<<<6400, 256>>>(x, wdef);
    k_offconv<<<256, 256>>>(x, woff);
    k_mainMMA<<<256, 256, SMEM_TOTAL>>>(boff, gamma, beta, out);
}

// round 10
// speedup vs baseline: 1.6667x; 1.0552x over previous
#include <cuda_runtime.h>
#include <cuda_fp16.h>
#include <stdint.h>
#include <math.h>

// ---------------------------------------------------------------------------
// Scratch (__device__ globals -- no allocation allowed)
// ---------------------------------------------------------------------------
__device__ float g_offp[4][18 * 16384];        // partial offset-conv sums
__device__ float g_xT[4 * 4096 * 256];         // x transposed [b][h*w][c]
__device__ __align__(16) unsigned char g_wbf[36 * 65536]; // per-chunk swizzled fp16 Bh/Bl (w*16)
__device__ double g_sum[256], g_sum2[256];
__device__ int g_barrier;

#define SWZ(x) ((x) ^ (((x) >> 3) & 0x70))
#define WSCALE 16.0f

__device__ __forceinline__ uint32_t smem_to_u32(const void* p) {
    uint32_t a;
    asm("{ .reg .u64 t; cvta.to.shared.u64 t, %1; cvt.u32.u64 %0, t; }" : "=r"(a) : "l"(p));
    return a;
}

__device__ __forceinline__ void ldsm_x4(uint32_t* r, uint32_t addr) {
    asm volatile("ldmatrix.sync.aligned.m8n8.x4.shared.b16 {%0,%1,%2,%3}, [%4];"
                 : "=r"(r[0]), "=r"(r[1]), "=r"(r[2]), "=r"(r[3]) : "r"(addr));
}

__device__ __forceinline__ void mma_f16(float* d, const uint32_t* a, const uint32_t* b) {
    asm volatile("mma.sync.aligned.m16n8k16.row.col.f32.f16.f16.f32 "
                 "{%0,%1,%2,%3}, {%4,%5,%6,%7}, {%8,%9}, {%0,%1,%2,%3};"
                 : "+f"(d[0]), "+f"(d[1]), "+f"(d[2]), "+f"(d[3])
                 : "r"(a[0]), "r"(a[1]), "r"(a[2]), "r"(a[3]), "r"(b[0]), "r"(b[1]));
}

__device__ __forceinline__ void cp_async16(uint32_t smem_addr, const void* gmem) {
    asm volatile("cp.async.cg.shared.global [%0], [%1], 16;"
                 :: "r"(smem_addr), "l"(gmem));
}
#define CP_COMMIT() asm volatile("cp.async.commit_group;" ::: "memory")
#define CP_WAIT0()  asm volatile("cp.async.wait_group 0;" ::: "memory")
#define CP_WAIT1()  asm volatile("cp.async.wait_group 1;" ::: "memory")

// ---------------------------------------------------------------------------
// Kernel 0 (merged prep): blocks [0,4096) transpose x -> g_xT [b][hw][c];
// blocks [4096,6400) build swizzled fp16 hi/lo B tiles (w*16) + reset sums.
// ---------------------------------------------------------------------------
__global__ void k_prep(const float* __restrict__ x, const float* __restrict__ wdef) {
    __shared__ float t[32][33];
    if (blockIdx.x < 4096) {
        int bid = blockIdx.x;
        int b = bid >> 10, c0 = ((bid >> 7) & 7) * 32, s0 = (bid & 127) * 32;
        int si = threadIdx.x & 31, ci = threadIdx.x >> 5;
#pragma unroll
        for (int i = 0; i < 4; i++)
            t[ci + i * 8][si] = x[((size_t)b * 256 + c0 + ci + i * 8) * 4096 + s0 + si];
        __syncthreads();
        float* dst = g_xT + (size_t)b * (4096 * 256) + (size_t)s0 * 256 + c0;
#pragma unroll
        for (int i = 0; i < 4; i++)
            dst[(size_t)(ci + i * 8) * 256 + si] = t[si][ci + i * 8];
    } else {
        int v = (blockIdx.x - 4096) * 256 + threadIdx.x;   // 2304*256 = 589824
        if (v < 256) { g_sum[v] = 0.0; g_sum2[v] = 0.0; }
        if (v == 0) g_barrier = 0;
        int cl = v & 63;
        int o  = (v >> 6) & 255;
        int chunk = v >> 14;
        int k2 = chunk >> 2, cc = chunk & 3;
        int c = cc * 64 + cl;
        float a = wdef[((size_t)o * 256 + c) * 9 + k2] * WSCALE;
        __half hi = __float2half_rn(a);
        __half lo = __float2half_rn(a - __half2float(hi));
        uint32_t byte = ((uint32_t)o << 7) + ((uint32_t)cl << 1);
        uint32_t sw = SWZ(byte);
        unsigned char* base = g_wbf + (size_t)chunk * 65536;
        *(__half*)(base + sw) = hi;
        *(__half*)(base + 32768 + sw) = lo;
    }
}

// ---------------------------------------------------------------------------
// Kernel 1: offset conv (18 out ch, 3x3, pad 1), smem-tiled.
// block = 16x16 px tile; per channel: stage 18x18 halo patch in smem
// (324 elems, strided over 256 threads -- R9 bug was tid<324 single shot).
// grid 256 = 4 c-chunks x 4 b x 16 tiles.
// ---------------------------------------------------------------------------
__global__ void __launch_bounds__(256) k_offconv(const float* __restrict__ x,
                                                 const float* __restrict__ woff) {
    __shared__ float Wsh[18 * 64 * 9];   // 41472 B
    __shared__ float patch[18 * 18];

    int chunk = blockIdx.x >> 6;
    int b     = (blockIdx.x >> 4) & 3;
    int tile  = blockIdx.x & 15;
    int h0 = (tile >> 2) * 16, w0 = (tile & 3) * 16;
    int c0 = chunk * 64;
    int tid = threadIdx.x;
    int ty = tid >> 4, tx = tid & 15;

    for (int v = tid; v < 18 * 576; v += 256) {
        int oc = v / 576;
        int rem = v % 576;
        Wsh[v] = woff[oc * 2304 + c0 * 9 + rem];
    }

    float acc[18];
#pragma unroll
    for (int i = 0; i < 18; i++) acc[i] = 0.f;

    const float* xb = x + ((size_t)b * 256 + c0) * 4096;
    __syncthreads();

    for (int cl = 0; cl < 64; cl++) {
        const float* xc = xb + (size_t)cl * 4096;
        // stage 18x18 halo patch (324 elements, 2 strided passes)
        for (int v = tid; v < 324; v += 256) {
            int r = v / 18, cc_ = v % 18;
            int gh = h0 - 1 + r, gw = w0 - 1 + cc_;
            bool ok = (gh >= 0) && (gh < 64) && (gw >= 0) && (gw < 64);
            patch[v] = ok ? xc[gh * 64 + gw] : 0.f;
        }
        __syncthreads();

        float xr[9];
#pragma unroll
        for (int dy = 0; dy < 3; dy++)
#pragma unroll
            for (int dx = 0; dx < 3; dx++)
                xr[dy * 3 + dx] = patch[(ty + dy) * 18 + (tx + dx)];

        const float* wp = Wsh + cl * 9;
#pragma unroll
        for (int oc = 0; oc < 18; oc++) {
            const float* wo = wp + oc * 576;
            float s = acc[oc];
#pragma unroll
            for (int t = 0; t < 9; t++) s += xr[t] * wo[t];
            acc[oc] = s;
        }
        __syncthreads();
    }

    int hw = (h0 + ty) * 64 + (w0 + tx);
#pragma unroll
    for (int oc = 0; oc < 18; oc++)
        g_offp[chunk][(b * 18 + oc) * 4096 + hw] = acc[oc];
}

// ---------------------------------------------------------------------------
// Kernel 2: fully fused main: gather + fp16 GEMM (A single, B hi/lo x16) +
// BN stats + grid barrier + normalize + ReLU + direct coalesced output.
// CTA = 128 px x 128 o.  Grid 256 (all co-resident at 2 CTAs/SM).
// ---------------------------------------------------------------------------
#define A_OFF 0
#define B0_HI 16384
#define B1_HI 49152
// lo tile always at hi + 16384
#define SWT_OFF 81920
#define SIX_OFF 83968
#define SMEM_TOTAL 86016
// epilogue reuse: stage[128][130] floats at offset 0 (66560 B); sc/sh at SWT_OFF

__global__ void __launch_bounds__(256, 2) k_mainMMA(const float* __restrict__ boff,
                                                    const float* __restrict__ gamma,
                                                    const float* __restrict__ beta,
                                                    float* __restrict__ out) {
    extern __shared__ __align__(128) char smem[];
    uint32_t sb32 = smem_to_u32(smem);
    float* sWt = (float*)(smem + SWT_OFF);   // [4][128]
    int*   sIx = (int*)(smem + SIX_OFF);     // [4][128]

    int tid = threadIdx.x, lane = tid & 31, wid = tid >> 5;
    int wm = wid & 3, wn = wid >> 2;
    int pt = blockIdx.x >> 1, nh = blockIdx.x & 1;
    int b = pt >> 5, h0 = (pt & 31) * 2;
    int n0 = nh * 128;

    float acc[2][8][4];
#pragma unroll
    for (int mt = 0; mt < 2; mt++)
#pragma unroll
        for (int j = 0; j < 8; j++)
#pragma unroll
            for (int r = 0; r < 4; r++) acc[mt][j][r] = 0.f;

    const float* xTb = g_xT + (size_t)b * (4096 * 256);

    // prefetch B chunk 0 into buffer 0
    {
        const char* srch = (const char*)g_wbf + (size_t)n0 * 128;
        const char* srcl = srch + 32768;
#pragma unroll
        for (int t = 0; t < 4; t++) {
            uint32_t off = (uint32_t)(t * 256 + tid) * 16;
            cp_async16(sb32 + B0_HI + off, srch + off);
            cp_async16(sb32 + B0_HI + 16384 + off, srcl + off);
        }
        CP_COMMIT();
    }

    for (int i = 0; i < 36; i++) {
        int k2 = i >> 2, cc = i & 3;
        uint32_t bbase = (i & 1) ? B1_HI : B0_HI;

        if (cc == 0) {
            if (tid < 128) {
                int px = tid;
                int h = h0 + (px >> 6), w = px & 63;
                int iy_ = (b * 18 + 2 * k2) * 4096 + h * 64 + w;
                int ix_ = iy_ + 4096;
                float offy = g_offp[0][iy_] + g_offp[1][iy_] + g_offp[2][iy_] + g_offp[3][iy_] + boff[2 * k2];
                float offx = g_offp[0][ix_] + g_offp[1][ix_] + g_offp[2][ix_] + g_offp[3][ix_] + boff[2 * k2 + 1];
                float py  = offy + (float)(k2 / 3) + (float)h - 1.0f;
                float pxx = offx + (float)(k2 % 3) + (float)w - 1.0f;
                float y0f = floorf(py), x0f = floorf(pxx);
                float wy1 = py - y0f, wx1 = pxx - x0f;
                float wy0 = 1.f - wy1, wx0 = 1.f - wx1;
                bool vy0 = (y0f >= 0.f)       && (y0f <= 63.f);
                bool vy1 = (y0f + 1.f >= 0.f) && (y0f + 1.f <= 63.f);
                bool vx0 = (x0f >= 0.f)       && (x0f <= 63.f);
                bool vx1 = (x0f + 1.f >= 0.f) && (x0f + 1.f <= 63.f);
                int iy0 = min(max((int)y0f, 0), 63);
                int iy1 = min(max((int)y0f + 1, 0), 63);
                int ix0 = min(max((int)x0f, 0), 63);
                int ix1 = min(max((int)x0f + 1, 0), 63);
                sIx[0 * 128 + px] = iy0 * 64 + ix0;  sWt[0 * 128 + px] = (vy0 && vx0) ? wy0 * wx0 : 0.f;
                sIx[1 * 128 + px] = iy0 * 64 + ix1;  sWt[1 * 128 + px] = (vy0 && vx1) ? wy0 * wx1 : 0.f;
                sIx[2 * 128 + px] = iy1 * 64 + ix0;  sWt[2 * 128 + px] = (vy1 && vx0) ? wy1 * wx0 : 0.f;
                sIx[3 * 128 + px] = iy1 * 64 + ix1;  sWt[3 * 128 + px] = (vy1 && vx1) ? wy1 * wx1 : 0.f;
            }
            __syncthreads();
        }

        // gather A: 128 px x 64 c (bilinear, 4 corners, float4 over c) -> fp16
        int c0 = cc * 64;
#pragma unroll
        for (int t = 0; t < 8; t++) {
            int task = t * 256 + tid;
            int px = task >> 4;
            int cl = (task & 15) * 4;
            float w0 = sWt[0 * 128 + px], w1 = sWt[1 * 128 + px];
            float w2 = sWt[2 * 128 + px], w3 = sWt[3 * 128 + px];
            const float4 v0 = *(const float4*)(xTb + (size_t)sIx[0 * 128 + px] * 256 + c0 + cl);
            const float4 v1 = *(const float4*)(xTb + (size_t)sIx[1 * 128 + px] * 256 + c0 + cl);
            const float4 v2 = *(const float4*)(xTb + (size_t)sIx[2 * 128 + px] * 256 + c0 + cl);
            const float4 v3 = *(const float4*)(xTb + (size_t)sIx[3 * 128 + px] * 256 + c0 + cl);
            float a0 = w0 * v0.x + w1 * v1.x + w2 * v2.x + w3 * v3.x;
            float a1 = w0 * v0.y + w1 * v1.y + w2 * v2.y + w3 * v3.y;
            float a2 = w0 * v0.z + w1 * v1.z + w2 * v2.z + w3 * v3.z;
            float a3 = w0 * v0.w + w1 * v1.w + w2 * v2.w + w3 * v3.w;
            __half2 p01 = __floats2half2_rn(a0, a1);
            __half2 p23 = __floats2half2_rn(a2, a3);
            uint2 hv;
            hv.x = *(uint32_t*)&p01;
            hv.y = *(uint32_t*)&p23;
            uint32_t byte = ((uint32_t)px << 7) + ((uint32_t)cl << 1);
            uint32_t sw = SWZ(byte);
            *(uint2*)(smem + A_OFF + sw) = hv;
        }

        // prefetch next B chunk into the other buffer (overlaps current MMA)
        if (i < 35) {
            uint32_t nb = (i & 1) ? B0_HI : B1_HI;
            const char* srch = (const char*)g_wbf + (size_t)(i + 1) * 65536 + (size_t)n0 * 128;
            const char* srcl = srch + 32768;
#pragma unroll
            for (int t = 0; t < 4; t++) {
                uint32_t off = (uint32_t)(t * 256 + tid) * 16;
                cp_async16(sb32 + nb + off, srch + off);
                cp_async16(sb32 + nb + 16384 + off, srcl + off);
            }
            CP_COMMIT();
            CP_WAIT1();        // current chunk's B resident
        } else {
            CP_WAIT0();
        }
        __syncthreads();

        // MMA: 4 k16 steps, 2 products (A*Bh + A*Bl)
#pragma unroll
        for (int k16 = 0; k16 < 4; k16++) {
            uint32_t ah[2][4];
#pragma unroll
            for (int mt = 0; mt < 2; mt++) {
                int arow = wm * 32 + mt * 16 + (lane & 15);
                int acb  = k16 * 32 + ((lane >> 4) << 4);
                uint32_t off = SWZ((uint32_t)(arow * 128 + acb));
                ldsm_x4(ah[mt], sb32 + A_OFF + off);
            }
#pragma unroll
            for (int np = 0; np < 4; np++) {
                uint32_t bh[4], bl[4];
                int brow = wn * 64 + np * 16 + ((lane >> 4) << 3) + (lane & 7);
                int bcb  = k16 * 32 + ((lane & 8) << 1);
                uint32_t off = SWZ((uint32_t)(brow * 128 + bcb));
                ldsm_x4(bh, sb32 + bbase + off);
                ldsm_x4(bl, sb32 + bbase + 16384 + off);
#pragma unroll
                for (int mt = 0; mt < 2; mt++)
#pragma unroll
                    for (int jj = 0; jj < 2; jj++) {
                        int j = np * 2 + jj;
                        mma_f16(acc[mt][j], ah[mt], &bh[jj * 2]);
                        mma_f16(acc[mt][j], ah[mt], &bl[jj * 2]);
                    }
            }
        }
        __syncthreads();
    }

    // -------- fused BN column stats (scaled x16 values) --------
    float* ssum  = (float*)smem;             // [128]
    float* ssum2 = (float*)(smem + 1024);    // [128]
    if (tid < 128) { ssum[tid] = 0.f; ssum2[tid] = 0.f; }
    __syncthreads();

    float ls[16], ls2[16];
#pragma unroll
    for (int v = 0; v < 16; v++) { ls[v] = 0.f; ls2[v] = 0.f; }
#pragma unroll
    for (int mt = 0; mt < 2; mt++)
#pragma unroll
        for (int j = 0; j < 8; j++) {
            float a0 = acc[mt][j][0], a1 = acc[mt][j][1];
            float a2 = acc[mt][j][2], a3 = acc[mt][j][3];
            ls[j * 2]      += a0 + a2;
            ls[j * 2 + 1]  += a1 + a3;
            ls2[j * 2]     += a0 * a0 + a2 * a2;
            ls2[j * 2 + 1] += a1 * a1 + a3 * a3;
        }
#pragma unroll
    for (int v = 0; v < 16; v++) {
        int ol = wn * 64 + (v >> 1) * 8 + (lane & 3) * 2 + (v & 1);
        atomicAdd(&ssum[ol], ls[v]);
        atomicAdd(&ssum2[ol], ls2[v]);
    }
    __syncthreads();
    if (tid < 128) {
        atomicAdd(&g_sum[n0 + tid], (double)ssum[tid]);
        atomicAdd(&g_sum2[n0 + tid], (double)ssum2[tid]);
    }

    // -------- grid-wide barrier (all 256 CTAs co-resident) --------
    __syncthreads();
    if (tid == 0) {
        __threadfence();
        atomicAdd(&g_barrier, 1);
        while (*(volatile int*)&g_barrier < 256) { }
        __threadfence();
    }
    __syncthreads();

    // -------- per-channel scale/shift (descale x16 exactly) --------
    float* sc = (float*)(smem + SWT_OFF);        // [128]  (applied to scaled vals)
    float* sh = (float*)(smem + SWT_OFF + 512);  // [128]
    if (tid < 128) {
        int o = n0 + tid;
        double mean = g_sum[o] / (16384.0 * (double)WSCALE);
        double var  = g_sum2[o] / (16384.0 * (double)WSCALE * (double)WSCALE) - mean * mean;
        float s = gamma[o] * rsqrtf((float)var + 1e-5f);
        sc[tid] = s / WSCALE;
        sh[tid] = beta[o] - (float)mean * s;
    }

    // -------- stage acc -> smem [o_local][px] (stride 130) --------
    float* stage = (float*)smem;
    __syncthreads();
#pragma unroll
    for (int mt = 0; mt < 2; mt++)
#pragma unroll
        for (int j = 0; j < 8; j++) {
            int px = wm * 32 + mt * 16 + (lane >> 2);
            int ol = wn * 64 + j * 8 + (lane & 3) * 2;
            stage[ol * 130 + px]           = acc[mt][j][0];
            stage[(ol + 1) * 130 + px]     = acc[mt][j][1];
            stage[ol * 130 + px + 8]       = acc[mt][j][2];
            stage[(ol + 1) * 130 + px + 8] = acc[mt][j][3];
        }
    __syncthreads();

    // -------- normalize + ReLU + direct coalesced write to out --------
    size_t obase = ((size_t)b * 256 + n0) * 4096 + (size_t)h0 * 64;
#pragma unroll
    for (int it = 0; it < 64; it++) {
        int gi = it * 256 + tid;
        int o  = gi >> 7;
        int px = gi & 127;
        float v = stage[o * 130 + px] * sc[o] + sh[o];
        out[obase + (size_t)o * 4096 + px] = fmaxf(v, 0.f);
    }
}

// ---------------------------------------------------------------------------
extern "C" void kernel_launch(void* const* d_in, const int* in_sizes, int n_in,
                              void* d_out, int out_size) {
    const float* x     = (const float*)d_in[0];
    const float* woff  = (const float*)d_in[1];
    const float* boff  = (const float*)d_in[2];
    const float* wdef  = (const float*)d_in[3];
    const float* gamma = (const float*)d_in[4];
    const float* beta  = (const float*)d_in[5];
    float* out = (float*)d_out;

    cudaFuncSetAttribute(k_mainMMA, cudaFuncAttributeMaxDynamicSharedMemorySize, SMEM_TOTAL);

    k_prep<<<6400, 256>>>(x, wdef);
    k_offconv<<<256, 256>>>(x, woff);
    k_mainMMA<<<256, 256, SMEM_TOTAL>>>(boff, gamma, beta, out);
}

// round 12
// speedup vs baseline: 1.8685x; 1.1211x over previous
#include <cuda_runtime.h>
#include <cuda_fp16.h>
#include <stdint.h>
#include <math.h>

// ---------------------------------------------------------------------------
// Scratch (__device__ globals -- no allocation allowed)
// ---------------------------------------------------------------------------
__device__ float g_offp[4][18 * 16384];        // partial offset-conv sums
__device__ __half g_xTh[4 * 4096 * 256];       // x transposed [b][h*w][c], fp16
__device__ __align__(16) unsigned char g_wbf[36 * 65536]; // per-chunk swizzled fp16 Bh/Bl (w*16)
__device__ double g_sum[256], g_sum2[256];
__device__ int g_barrier;

#define SWZ(x) ((x) ^ (((x) >> 3) & 0x70))
#define WSCALE 16.0f

__device__ __forceinline__ uint32_t smem_to_u32(const void* p) {
    uint32_t a;
    asm("{ .reg .u64 t; cvta.to.shared.u64 t, %1; cvt.u32.u64 %0, t; }" : "=r"(a) : "l"(p));
    return a;
}

__device__ __forceinline__ void ldsm_x4(uint32_t* r, uint32_t addr) {
    asm volatile("ldmatrix.sync.aligned.m8n8.x4.shared.b16 {%0,%1,%2,%3}, [%4];"
                 : "=r"(r[0]), "=r"(r[1]), "=r"(r[2]), "=r"(r[3]) : "r"(addr));
}

__device__ __forceinline__ void mma_f16(float* d, const uint32_t* a, const uint32_t* b) {
    asm volatile("mma.sync.aligned.m16n8k16.row.col.f32.f16.f16.f32 "
                 "{%0,%1,%2,%3}, {%4,%5,%6,%7}, {%8,%9}, {%0,%1,%2,%3};"
                 : "+f"(d[0]), "+f"(d[1]), "+f"(d[2]), "+f"(d[3])
                 : "r"(a[0]), "r"(a[1]), "r"(a[2]), "r"(a[3]), "r"(b[0]), "r"(b[1]));
}

__device__ __forceinline__ void cp_async16(uint32_t smem_addr, const void* gmem) {
    asm volatile("cp.async.cg.shared.global [%0], [%1], 16;"
                 :: "r"(smem_addr), "l"(gmem));
}
#define CP_COMMIT() asm volatile("cp.async.commit_group;" ::: "memory")
#define CP_WAIT0()  asm volatile("cp.async.wait_group 0;" ::: "memory")
#define CP_WAIT1()  asm volatile("cp.async.wait_group 1;" ::: "memory")

// ---------------------------------------------------------------------------
// Kernel 0 (merged prep): blocks [0,4096) transpose x -> g_xTh [b][hw][c] fp16;
// blocks [4096,6400) build swizzled fp16 hi/lo B tiles (w*16) + reset sums.
// ---------------------------------------------------------------------------
__global__ void k_prep(const float* __restrict__ x, const float* __restrict__ wdef) {
    __shared__ float t[32][33];
    if (blockIdx.x < 4096) {
        int bid = blockIdx.x;
        int b = bid >> 10, c0 = ((bid >> 7) & 7) * 32, s0 = (bid & 127) * 32;
        int si = threadIdx.x & 31, ci = threadIdx.x >> 5;
#pragma unroll
        for (int i = 0; i < 4; i++)
            t[ci + i * 8][si] = x[((size_t)b * 256 + c0 + ci + i * 8) * 4096 + s0 + si];
        __syncthreads();
        __half* dst = g_xTh + (size_t)b * (4096 * 256) + (size_t)s0 * 256 + c0;
#pragma unroll
        for (int i = 0; i < 4; i++)
            dst[(size_t)(ci + i * 8) * 256 + si] = __float2half_rn(t[si][ci + i * 8]);
    } else {
        int v = (blockIdx.x - 4096) * 256 + threadIdx.x;   // 2304*256 = 589824
        if (v < 256) { g_sum[v] = 0.0; g_sum2[v] = 0.0; }
        if (v == 0) g_barrier = 0;
        int cl = v & 63;
        int o  = (v >> 6) & 255;
        int chunk = v >> 14;
        int k2 = chunk >> 2, cc = chunk & 3;
        int c = cc * 64 + cl;
        float a = wdef[((size_t)o * 256 + c) * 9 + k2] * WSCALE;
        __half hi = __float2half_rn(a);
        __half lo = __float2half_rn(a - __half2float(hi));
        uint32_t byte = ((uint32_t)o << 7) + ((uint32_t)cl << 1);
        uint32_t sw = SWZ(byte);
        unsigned char* base = g_wbf + (size_t)chunk * 65536;
        *(__half*)(base + sw) = hi;
        *(__half*)(base + 32768 + sw) = lo;
    }
}

// ---------------------------------------------------------------------------
// Kernel 1: offset conv (18 out ch, 3x3, pad 1), smem-tiled.
// block = 16x16 px tile; per channel: stage 18x18 halo patch in smem (strided).
// grid 256 = 4 c-chunks x 4 b x 16 tiles.
// ---------------------------------------------------------------------------
__global__ void __launch_bounds__(256) k_offconv(const float* __restrict__ x,
                                                 const float* __restrict__ woff) {
    __shared__ float Wsh[18 * 64 * 9];   // 41472 B
    __shared__ float patch[18 * 18];

    int chunk = blockIdx.x >> 6;
    int b     = (blockIdx.x >> 4) & 3;
    int tile  = blockIdx.x & 15;
    int h0 = (tile >> 2) * 16, w0 = (tile & 3) * 16;
    int c0 = chunk * 64;
    int tid = threadIdx.x;
    int ty = tid >> 4, tx = tid & 15;

    for (int v = tid; v < 18 * 576; v += 256) {
        int oc = v / 576;
        int rem = v % 576;
        Wsh[v] = woff[oc * 2304 + c0 * 9 + rem];
    }

    float acc[18];
#pragma unroll
    for (int i = 0; i < 18; i++) acc[i] = 0.f;

    const float* xb = x + ((size_t)b * 256 + c0) * 4096;
    __syncthreads();

    for (int cl = 0; cl < 64; cl++) {
        const float* xc = xb + (size_t)cl * 4096;
        for (int v = tid; v < 324; v += 256) {
            int r = v / 18, cc_ = v % 18;
            int gh = h0 - 1 + r, gw = w0 - 1 + cc_;
            bool ok = (gh >= 0) && (gh < 64) && (gw >= 0) && (gw < 64);
            patch[v] = ok ? xc[gh * 64 + gw] : 0.f;
        }
        __syncthreads();

        float xr[9];
#pragma unroll
        for (int dy = 0; dy < 3; dy++)
#pragma unroll
            for (int dx = 0; dx < 3; dx++)
                xr[dy * 3 + dx] = patch[(ty + dy) * 18 + (tx + dx)];

        const float* wp = Wsh + cl * 9;
#pragma unroll
        for (int oc = 0; oc < 18; oc++) {
            const float* wo = wp + oc * 576;
            float s = acc[oc];
#pragma unroll
            for (int t = 0; t < 9; t++) s += xr[t] * wo[t];
            acc[oc] = s;
        }
        __syncthreads();
    }

    int hw = (h0 + ty) * 64 + (w0 + tx);
#pragma unroll
    for (int oc = 0; oc < 18; oc++)
        g_offp[chunk][(b * 18 + oc) * 4096 + hw] = acc[oc];
}

// ---------------------------------------------------------------------------
// Kernel 2: fully fused main: half2 gather + fp16 GEMM (A single, B hi/lo x16)
// + BN stats + grid barrier + normalize + ReLU + direct coalesced output.
// CTA = 128 px x 128 o.  Grid 256 (all co-resident at 2 CTAs/SM).
// ---------------------------------------------------------------------------
#define A_OFF 0
#define B0_HI 16384
#define B1_HI 49152
// lo tile always at hi + 16384
#define SWTH_OFF 81920
#define SIX_OFF 83968
#define SMEM_TOTAL 86016
// epilogue reuse: stage[128][130] floats at offset 0 (66560 B); sc/sh at SWTH_OFF

__global__ void __launch_bounds__(256, 2) k_mainMMA(const float* __restrict__ boff,
                                                    const float* __restrict__ gamma,
                                                    const float* __restrict__ beta,
                                                    float* __restrict__ out) {
    extern __shared__ __align__(128) char smem[];
    uint32_t sb32 = smem_to_u32(smem);
    __half2* sWtH = (__half2*)(smem + SWTH_OFF);  // [4][128] broadcast weights
    int*     sIx  = (int*)(smem + SIX_OFF);       // [4][128]

    int tid = threadIdx.x, lane = tid & 31, wid = tid >> 5;
    int wm = wid & 3, wn = wid >> 2;
    int pt = blockIdx.x >> 1, nh = blockIdx.x & 1;
    int b = pt >> 5, h0 = (pt & 31) * 2;
    int n0 = nh * 128;

    float acc[2][8][4];
#pragma unroll
    for (int mt = 0; mt < 2; mt++)
#pragma unroll
        for (int j = 0; j < 8; j++)
#pragma unroll
            for (int r = 0; r < 4; r++) acc[mt][j][r] = 0.f;

    const __half* xTb = g_xTh + (size_t)b * (4096 * 256);

    // prefetch B chunk 0 into buffer 0
    {
        const char* srch = (const char*)g_wbf + (size_t)n0 * 128;
        const char* srcl = srch + 32768;
#pragma unroll
        for (int t = 0; t < 4; t++) {
            uint32_t off = (uint32_t)(t * 256 + tid) * 16;
            cp_async16(sb32 + B0_HI + off, srch + off);
            cp_async16(sb32 + B0_HI + 16384 + off, srcl + off);
        }
        CP_COMMIT();
    }

    for (int i = 0; i < 36; i++) {
        int k2 = i >> 2, cc = i & 3;
        uint32_t bbase = (i & 1) ? B1_HI : B0_HI;

        if (cc == 0) {
            if (tid < 128) {
                int px = tid;
                int h = h0 + (px >> 6), w = px & 63;
                int iy_ = (b * 18 + 2 * k2) * 4096 + h * 64 + w;
                int ix_ = iy_ + 4096;
                float offy = g_offp[0][iy_] + g_offp[1][iy_] + g_offp[2][iy_] + g_offp[3][iy_] + boff[2 * k2];
                float offx = g_offp[0][ix_] + g_offp[1][ix_] + g_offp[2][ix_] + g_offp[3][ix_] + boff[2 * k2 + 1];
                float py  = offy + (float)(k2 / 3) + (float)h - 1.0f;
                float pxx = offx + (float)(k2 % 3) + (float)w - 1.0f;
                float y0f = floorf(py), x0f = floorf(pxx);
                float wy1 = py - y0f, wx1 = pxx - x0f;
                float wy0 = 1.f - wy1, wx0 = 1.f - wx1;
                bool vy0 = (y0f >= 0.f)       && (y0f <= 63.f);
                bool vy1 = (y0f + 1.f >= 0.f) && (y0f + 1.f <= 63.f);
                bool vx0 = (x0f >= 0.f)       && (x0f <= 63.f);
                bool vx1 = (x0f + 1.f >= 0.f) && (x0f + 1.f <= 63.f);
                int iy0 = min(max((int)y0f, 0), 63);
                int iy1 = min(max((int)y0f + 1, 0), 63);
                int ix0 = min(max((int)x0f, 0), 63);
                int ix1 = min(max((int)x0f + 1, 0), 63);
                float w0f = (vy0 && vx0) ? wy0 * wx0 : 0.f;
                float w1f = (vy0 && vx1) ? wy0 * wx1 : 0.f;
                float w2f = (vy1 && vx0) ? wy1 * wx0 : 0.f;
                float w3f = (vy1 && vx1) ? wy1 * wx1 : 0.f;
                sIx[0 * 128 + px] = iy0 * 64 + ix0;  sWtH[0 * 128 + px] = __half2half2(__float2half_rn(w0f));
                sIx[1 * 128 + px] = iy0 * 64 + ix1;  sWtH[1 * 128 + px] = __half2half2(__float2half_rn(w1f));
                sIx[2 * 128 + px] = iy1 * 64 + ix0;  sWtH[2 * 128 + px] = __half2half2(__float2half_rn(w2f));
                sIx[3 * 128 + px] = iy1 * 64 + ix1;  sWtH[3 * 128 + px] = __half2half2(__float2half_rn(w3f));
            }
            __syncthreads();
        }

        // gather A: 128 px x 64 c, 8 channels/task via uint4 fp16 loads,
        // bilinear in half2 ISA.  1024 tasks = 4 iters x 256 threads.
        int c0 = cc * 64;
#pragma unroll
        for (int t = 0; t < 4; t++) {
            int task = t * 256 + tid;
            int px = task >> 3;
            int cl = (task & 7) * 8;
            __half2 w0h = sWtH[0 * 128 + px], w1h = sWtH[1 * 128 + px];
            __half2 w2h = sWtH[2 * 128 + px], w3h = sWtH[3 * 128 + px];
            const uint4 v0 = *(const uint4*)(xTb + (size_t)sIx[0 * 128 + px] * 256 + c0 + cl);
            const uint4 v1 = *(const uint4*)(xTb + (size_t)sIx[1 * 128 + px] * 256 + c0 + cl);
            const uint4 v2 = *(const uint4*)(xTb + (size_t)sIx[2 * 128 + px] * 256 + c0 + cl);
            const uint4 v3 = *(const uint4*)(xTb + (size_t)sIx[3 * 128 + px] * 256 + c0 + cl);
            uint4 r;
#define BILIN(dst, f)                                                          \
            {                                                                  \
                __half2 a_ = __hmul2(*(const __half2*)&v0.f, w0h);             \
                a_ = __hfma2(*(const __half2*)&v1.f, w1h, a_);                 \
                a_ = __hfma2(*(const __half2*)&v2.f, w2h, a_);                 \
                a_ = __hfma2(*(const __half2*)&v3.f, w3h, a_);                 \
                dst = *(uint32_t*)&a_;                                         \
            }
            BILIN(r.x, x) BILIN(r.y, y) BILIN(r.z, z) BILIN(r.w, w)
#undef BILIN
            uint32_t byte = ((uint32_t)px << 7) + ((uint32_t)cl << 1);
            uint32_t sw = SWZ(byte);
            *(uint4*)(smem + A_OFF + sw) = r;
        }

        // prefetch next B chunk into the other buffer (overlaps current MMA)
        if (i < 35) {
            uint32_t nb = (i & 1) ? B0_HI : B1_HI;
            const char* srch = (const char*)g_wbf + (size_t)(i + 1) * 65536 + (size_t)n0 * 128;
            const char* srcl = srch + 32768;
#pragma unroll
            for (int t = 0; t < 4; t++) {
                uint32_t off = (uint32_t)(t * 256 + tid) * 16;
                cp_async16(sb32 + nb + off, srch + off);
                cp_async16(sb32 + nb + 16384 + off, srcl + off);
            }
            CP_COMMIT();
            CP_WAIT1();        // current chunk's B resident
        } else {
            CP_WAIT0();
        }
        __syncthreads();

        // MMA: 4 k16 steps, 2 products (A*Bh + A*Bl)
#pragma unroll
        for (int k16 = 0; k16 < 4; k16++) {
            uint32_t ah[2][4];
#pragma unroll
            for (int mt = 0; mt < 2; mt++) {
                int arow = wm * 32 + mt * 16 + (lane & 15);
                int acb  = k16 * 32 + ((lane >> 4) << 4);
                uint32_t off = SWZ((uint32_t)(arow * 128 + acb));
                ldsm_x4(ah[mt], sb32 + A_OFF + off);
            }
#pragma unroll
            for (int np = 0; np < 4; np++) {
                uint32_t bh[4], bl[4];
                int brow = wn * 64 + np * 16 + ((lane >> 4) << 3) + (lane & 7);
                int bcb  = k16 * 32 + ((lane & 8) << 1);
                uint32_t off = SWZ((uint32_t)(brow * 128 + bcb));
                ldsm_x4(bh, sb32 + bbase + off);
                ldsm_x4(bl, sb32 + bbase + 16384 + off);
#pragma unroll
                for (int mt = 0; mt < 2; mt++)
#pragma unroll
                    for (int jj = 0; jj < 2; jj++) {
                        int j = np * 2 + jj;
                        mma_f16(acc[mt][j], ah[mt], &bh[jj * 2]);
                        mma_f16(acc[mt][j], ah[mt], &bl[jj * 2]);
                    }
            }
        }
        __syncthreads();
    }

    // -------- fused BN column stats (scaled x16 values) --------
    float* ssum  = (float*)smem;             // [128]
    float* ssum2 = (float*)(smem + 1024);    // [128]
    if (tid < 128) { ssum[tid] = 0.f; ssum2[tid] = 0.f; }
    __syncthreads();

    float ls[16], ls2[16];
#pragma unroll
    for (int v = 0; v < 16; v++) { ls[v] = 0.f; ls2[v] = 0.f; }
#pragma unroll
    for (int mt = 0; mt < 2; mt++)
#pragma unroll
        for (int j = 0; j < 8; j++) {
            float a0 = acc[mt][j][0], a1 = acc[mt][j][1];
            float a2 = acc[mt][j][2], a3 = acc[mt][j][3];
            ls[j * 2]      += a0 + a2;
            ls[j * 2 + 1]  += a1 + a3;
            ls2[j * 2]     += a0 * a0 + a2 * a2;
            ls2[j * 2 + 1] += a1 * a1 + a3 * a3;
        }
#pragma unroll
    for (int v = 0; v < 16; v++) {
        int ol = wn * 64 + (v >> 1) * 8 + (lane & 3) * 2 + (v & 1);
        atomicAdd(&ssum[ol], ls[v]);
        atomicAdd(&ssum2[ol], ls2[v]);
    }
    __syncthreads();
    if (tid < 128) {
        atomicAdd(&g_sum[n0 + tid], (double)ssum[tid]);
        atomicAdd(&g_sum2[n0 + tid], (double)ssum2[tid]);
    }

    // -------- grid-wide barrier (all 256 CTAs co-resident) --------
    __syncthreads();
    if (tid == 0) {
        __threadfence();
        atomicAdd(&g_barrier, 1);
        while (*(volatile int*)&g_barrier < 256) { }
        __threadfence();
    }
    __syncthreads();

    // -------- per-channel scale/shift (descale x16 exactly) --------
    float* sc = (float*)(smem + SWTH_OFF);        // [128]  (applied to scaled vals)
    float* sh = (float*)(smem + SWTH_OFF + 512);  // [128]
    if (tid < 128) {
        int o = n0 + tid;
        double mean = g_sum[o] / (16384.0 * (double)WSCALE);
        double var  = g_sum2[o] / (16384.0 * (double)WSCALE * (double)WSCALE) - mean * mean;
        float s = gamma[o] * rsqrtf((float)var + 1e-5f);
        sc[tid] = s / WSCALE;
        sh[tid] = beta[o] - (float)mean * s;
    }

    // -------- stage acc -> smem [o_local][px] (stride 130) --------
    float* stage = (float*)smem;
    __syncthreads();
#pragma unroll
    for (int mt = 0; mt < 2; mt++)
#pragma unroll
        for (int j = 0; j < 8; j++) {
            int px = wm * 32 + mt * 16 + (lane >> 2);
            int ol = wn * 64 + j * 8 + (lane & 3) * 2;
            stage[ol * 130 + px]           = acc[mt][j][0];
            stage[(ol + 1) * 130 + px]     = acc[mt][j][1];
            stage[ol * 130 + px + 8]       = acc[mt][j][2];
            stage[(ol + 1) * 130 + px + 8] = acc[mt][j][3];
        }
    __syncthreads();

    // -------- normalize + ReLU + direct coalesced write to out --------
    size_t obase = ((size_t)b * 256 + n0) * 4096 + (size_t)h0 * 64;
#pragma unroll
    for (int it = 0; it < 64; it++) {
        int gi = it * 256 + tid;
        int o  = gi >> 7;
        int px = gi & 127;
        float v = stage[o * 130 + px] * sc[o] + sh[o];
        out[obase + (size_t)o * 4096 + px] = fmaxf(v, 0.f);
    }
}

// ---------------------------------------------------------------------------
extern "C" void kernel_launch(void* const* d_in, const int* in_sizes, int n_in,
                              void* d_out, int out_size) {
    const float* x     = (const float*)d_in[0];
    const float* woff  = (const float*)d_in[1];
    const float* boff  = (const float*)d_in[2];
    const float* wdef  = (const float*)d_in[3];
    const float* gamma = (const float*)d_in[4];
    const float* beta  = (const float*)d_in[5];
    float* out = (float*)d_out;

    cudaFuncSetAttribute(k_mainMMA, cudaFuncAttributeMaxDynamicSharedMemorySize, SMEM_TOTAL);

    k_prep<<<6400, 256>>>(x, wdef);
    k_offconv<<<256, 256>>>(x, woff);
    k_mainMMA<<<256, 256, SMEM_TOTAL>>>(boff, gamma, beta, out);
}